// round 9
// baseline (speedup 1.0000x reference)
#include <cuda_runtime.h>
#include <cstdint>

#define BATCH 8
#define CIN   64
#define COUT  64
#define Hdim  64
#define Wdim  64
#define CTOT  69
#define HW    (Hdim*Wdim)
#define NPIX  (BATCH*HW)

// Scratch (static device globals — no allocation)
__device__ float g_conv[BATCH*COUT*HW];   // raw conv output (pre-BN)
__device__ float g_sq[NPIX];              // 1x1-conv "shape query"
__device__ float g_mu[COUT];
__device__ float g_rs[COUT];
__device__ __align__(16) float g_wt[9*4096];  // weights in B-fragment order

__device__ __forceinline__ int clampi(int v, int lo, int hi) {
    return v < lo ? lo : (v > hi ? hi : v);
}
__device__ __forceinline__ float f2tf32f(float f) {
    uint32_t r; asm("cvt.rna.tf32.f32 %0, %1;" : "=r"(r) : "f"(f));
    return __uint_as_float(r);
}

// m16n8k8 tf32 mma: D += A*B (D==C, fp32 accum). a: 4 regs, b: 2 regs.
__device__ __forceinline__ void mma8(float* d, const uint32_t* a, uint32_t b0, uint32_t b1) {
    asm volatile(
        "mma.sync.aligned.m16n8k8.row.col.f32.tf32.tf32.f32 "
        "{%0,%1,%2,%3}, {%4,%5,%6,%7}, {%8,%9}, {%0,%1,%2,%3};\n"
        : "+f"(d[0]), "+f"(d[1]), "+f"(d[2]), "+f"(d[3])
        : "r"(a[0]), "r"(a[1]), "r"(a[2]), "r"(a[3]), "r"(b0), "r"(b1));
}

// ---------------------------------------------------------------------------
// Kernel 0: transform conv weights into B-fragment order (tf32-rounded).
// ---------------------------------------------------------------------------
__global__ __launch_bounds__(256) void wt_transform(const float* __restrict__ cw)
{
    int idx = blockIdx.x * 256 + threadIdx.x;
    if (idx >= 9 * 4096) return;
    int r    = idx & 1;
    int lane = (idx >> 1) & 31;
    int nt   = (idx >> 6) & 7;
    int kk   = (idx >> 9) & 7;
    int kidx = idx >> 12;
    int gid = lane >> 2, tig = lane & 3;
    int co = nt * 8 + gid;
    int ci = kk * 8 + tig + 4 * r;
    g_wt[idx] = f2tf32f(cw[(co * CIN + ci) * 9 + kidx]);
}

// ---------------------------------------------------------------------------
// Kernel 1: 3x3 conv (replication pad) via mma.sync tf32 implicit GEMM.
// (unchanged from the 57.3us version)
// ---------------------------------------------------------------------------
#define SLAB_STRIDE 264
#define SLAB_FLOATS (64*SLAB_STRIDE)          // 16896
#define BBUF_FLOATS 4096
#define DYN_SMEM ((SLAB_FLOATS + BBUF_FLOATS) * 4)   // 83968 B

__global__ __launch_bounds__(256, 2) void conv_mma_kernel(
    const float* __restrict__ x, const float* __restrict__ cb)
{
    extern __shared__ float smem[];
    float* slab = smem;                 // [64 ci][256 rc] stride 264
    float* bbuf = smem + SLAB_FLOATS;   // B fragments for current (ky,kx)

    const int tid  = threadIdx.x;
    const int lane = tid & 31;
    const int w    = tid >> 5;
    const int gid  = lane >> 2;
    const int tig  = lane & 3;
    const int wm   = (w & 3) * 32;      // pixel offset
    const int wn   = (w >> 2) * 32;     // cout offset
    const int blk  = blockIdx.x;
    const int b    = blk >> 5;
    const int h0   = (blk & 31) * 2;

    const float* xb = x + (size_t)b * CTOT * HW;
    #pragma unroll
    for (int i = 0; i < 64; i++) {
        int idx = i * 256 + tid;
        int ci  = idx >> 8;
        int rc  = idx & 255;
        int rr  = rc >> 6;
        int col = rc & 63;
        int row = clampi(h0 - 1 + rr, 0, Hdim - 1);
        slab[ci * SLAB_STRIDE + rc] = f2tf32f(__ldg(xb + (ci * Hdim + row) * Wdim + col));
    }

    const float4* wt4 = (const float4*)g_wt;
    float4 pf[4];
    #pragma unroll
    for (int j = 0; j < 4; j++) pf[j] = __ldg(wt4 + j * 256 + tid);

    float acc[2][4][4];
    #pragma unroll
    for (int tm = 0; tm < 2; tm++)
        #pragma unroll
        for (int nt = 0; nt < 4; nt++)
            #pragma unroll
            for (int c = 0; c < 4; c++) acc[tm][nt][c] = 0.f;

    __syncthreads();   // slab ready

    int dy[2], col_lo[2], col_hi[2];
    #pragma unroll
    for (int tm = 0; tm < 2; tm++) {
        int pix = wm + tm * 16 + gid;
        dy[tm] = pix >> 6;
        col_lo[tm] = pix & 63;
        col_hi[tm] = col_lo[tm] + 8;
    }

    float4* bb4 = (float4*)bbuf;

    for (int kidx = 0; kidx < 9; kidx++) {
        const int ky = kidx / 3, kx = kidx % 3;
        if (kidx > 0) __syncthreads();
        #pragma unroll
        for (int j = 0; j < 4; j++) bb4[j * 256 + tid] = pf[j];
        __syncthreads();
        if (kidx < 8) {
            #pragma unroll
            for (int j = 0; j < 4; j++)
                pf[j] = __ldg(wt4 + (kidx + 1) * 1024 + j * 256 + tid);
        }

        int off_lo[2], off_hi[2];
        #pragma unroll
        for (int tm = 0; tm < 2; tm++) {
            int rowoff = (dy[tm] + ky) * 64;
            off_lo[tm] = rowoff + clampi(col_lo[tm] + kx - 1, 0, 63);
            off_hi[tm] = rowoff + clampi(col_hi[tm] + kx - 1, 0, 63);
        }

        #pragma unroll
        for (int kk = 0; kk < 8; kk++) {
            const int cib  = (kk * 8 + tig) * SLAB_STRIDE;
            const int cib4 = cib + 4 * SLAB_STRIDE;
            uint32_t a[2][4];
            #pragma unroll
            for (int tm = 0; tm < 2; tm++) {
                a[tm][0] = __float_as_uint(slab[cib  + off_lo[tm]]);
                a[tm][1] = __float_as_uint(slab[cib  + off_hi[tm]]);
                a[tm][2] = __float_as_uint(slab[cib4 + off_lo[tm]]);
                a[tm][3] = __float_as_uint(slab[cib4 + off_hi[tm]]);
            }
            #pragma unroll
            for (int nt = 0; nt < 4; nt++) {
                int ntg = (wn >> 3) + nt;
                float2 bf = *(const float2*)&bbuf[((kk * 8 + ntg) * 32 + lane) * 2];
                uint32_t b0 = __float_as_uint(bf.x);
                uint32_t b1 = __float_as_uint(bf.y);
                mma8(acc[0][nt], a[0], b0, b1);
                mma8(acc[1][nt], a[1], b0, b1);
            }
        }
    }

    #pragma unroll
    for (int tm = 0; tm < 2; tm++) {
        float* grow = g_conv + ((size_t)b * COUT * Hdim + (h0 + dy[tm])) * Wdim;
        #pragma unroll
        for (int nt = 0; nt < 4; nt++) {
            int co0 = wn + nt * 8 + 2 * tig;
            float b0 = __ldg(cb + co0), b1 = __ldg(cb + co0 + 1);
            grow[(size_t)co0       * HW + col_lo[tm]] = acc[tm][nt][0] + b0;
            grow[(size_t)(co0 + 1) * HW + col_lo[tm]] = acc[tm][nt][1] + b1;
            grow[(size_t)co0       * HW + col_hi[tm]] = acc[tm][nt][2] + b0;
            grow[(size_t)(co0 + 1) * HW + col_hi[tm]] = acc[tm][nt][3] + b1;
        }
    }
}

// ---------------------------------------------------------------------------
// Kernel 2: BN stats, one block per channel, deterministic fixed-order tree
// ---------------------------------------------------------------------------
__global__ __launch_bounds__(256) void bn_stats()
{
    __shared__ float ss[256], ss2[256];
    const int co = blockIdx.x;
    const int t  = threadIdx.x;
    float s = 0.f, s2 = 0.f;
    #pragma unroll
    for (int b = 0; b < BATCH; b++) {
        const float4* p = (const float4*)(g_conv + ((size_t)(b * COUT + co)) * HW);
        #pragma unroll
        for (int j = 0; j < 4; j++) {
            float4 v = __ldg(p + t + j * 256);
            s  += v.x + v.y + v.z + v.w;
            s2 += v.x * v.x + v.y * v.y + v.z * v.z + v.w * v.w;
        }
    }
    ss[t] = s; ss2[t] = s2;
    __syncthreads();
    for (int o = 128; o > 0; o >>= 1) {
        if (t < o) { ss[t] += ss[t + o]; ss2[t] += ss2[t + o]; }
        __syncthreads();
    }
    if (t == 0) {
        float n   = (float)(BATCH * HW);
        float mu  = ss[0] / n;
        float var = ss2[0] / n - mu * mu;
        g_mu[co] = mu;
        g_rs[co] = rsqrtf(var + 1e-5f);
    }
}

// ---------------------------------------------------------------------------
// Kernel 3: codebook logits + channel softmax + BN-normalize + relu-attend
//           + 1x1 conv to shape query.
// 4 THREADS PER PIXEL: thread sub=tid&3 owns codes [sub*16, sub*16+16).
// Logits live in registers; softmax max/sum and sq combined across the quad
// with __shfl_xor (deterministic). logits = 2<sw,k> - |k|^2.
// ---------------------------------------------------------------------------
__global__ __launch_bounds__(256) void attend_kernel(
    const float* __restrict__ x, const float* __restrict__ sk,
    const float* __restrict__ c2w, const float* __restrict__ c2b,
    float* __restrict__ out)
{
    __shared__ __align__(16) float s_kT[45 * 64];   // [t][co]
    __shared__ float s_k2[64];
    __shared__ float s_w2[64];
    __shared__ float s_mu[64];
    __shared__ float s_rs[64];

    const int tid = threadIdx.x;
    for (int i = tid; i < 64 * 45; i += 256) {
        int co = i / 45, t = i - co * 45;
        s_kT[t * 64 + co] = sk[i];
    }
    if (tid < 64) { s_w2[tid] = c2w[tid]; s_mu[tid] = g_mu[tid]; s_rs[tid] = g_rs[tid]; }
    __syncthreads();
    if (tid < 64) {
        float a = 0.f;
        #pragma unroll
        for (int t2 = 0; t2 < 45; t2++) {
            float kv = s_kT[t2 * 64 + tid];
            a = fmaf(kv, kv, a);
        }
        s_k2[tid] = a;
    }
    __syncthreads();

    const int p   = blockIdx.x * 64 + (tid >> 2);   // pixel index
    const int sub = tid & 3;
    const int cbs = sub * 16;                        // code base for this thread
    const int b   = p >> 12;
    const int hw  = p & 4095;
    const int h   = hw >> 6;
    const int w   = hw & 63;

    // shape window (channels 64..68), replication-padded, center-subtracted
    float sw[45];
    #pragma unroll
    for (int c = 0; c < 5; c++) {
        #pragma unroll
        for (int i = 0; i < 3; i++)
            #pragma unroll
            for (int j = 0; j < 3; j++) {
                int gy = clampi(h + i - 1, 0, Hdim - 1);
                int gx = clampi(w + j - 1, 0, Wdim - 1);
                sw[c * 9 + i * 3 + j] = x[((b * CTOT + 64 + c) * Hdim + gy) * Wdim + gx];
            }
    }
    #pragma unroll
    for (int c = 0; c < 2; c++) {
        float ctr = sw[c * 9 + 4];
        #pragma unroll
        for (int k = 0; k < 9; k++) sw[c * 9 + k] -= ctr;
    }

    // ---- logits for this thread's 16 codes (4 ILP chains x 4 groups) ----
    float lg[16];
    #pragma unroll
    for (int j = 0; j < 16; j += 4) {
        float d0 = 0.f, d1 = 0.f, d2 = 0.f, d3 = 0.f;
        #pragma unroll
        for (int t2 = 0; t2 < 45; t2++) {
            float s = sw[t2];
            float4 k4 = *(const float4*)&s_kT[t2 * 64 + cbs + j];
            d0 = fmaf(s, k4.x, d0);
            d1 = fmaf(s, k4.y, d1);
            d2 = fmaf(s, k4.z, d2);
            d3 = fmaf(s, k4.w, d3);
        }
        float4 k2 = *(const float4*)&s_k2[cbs + j];
        lg[j]     = 2.f * d0 - k2.x;
        lg[j + 1] = 2.f * d1 - k2.y;
        lg[j + 2] = 2.f * d2 - k2.z;
        lg[j + 3] = 2.f * d3 - k2.w;
    }

    // ---- softmax across 64 codes (local 16 + quad shfl) ----
    float lmax = lg[0];
    #pragma unroll
    for (int j = 1; j < 16; j++) lmax = fmaxf(lmax, lg[j]);
    lmax = fmaxf(lmax, __shfl_xor_sync(0xffffffffu, lmax, 1));
    lmax = fmaxf(lmax, __shfl_xor_sync(0xffffffffu, lmax, 2));

    float se = 0.f;
    #pragma unroll
    for (int j = 0; j < 16; j++) {
        lg[j] = __expf(lg[j] - lmax);
        se += lg[j];
    }
    se += __shfl_xor_sync(0xffffffffu, se, 1);
    se += __shfl_xor_sync(0xffffffffu, se, 2);
    float inv = 1.f / se;

    // ---- attend + partial 1x1 conv over this thread's 16 codes ----
    const float* gc = g_conv + (size_t)b * COUT * HW + hw;
    float* op = out + (size_t)b * CTOT * HW + hw;
    float sq = 0.f;
    #pragma unroll
    for (int j = 0; j < 16; j++) {
        int co = cbs + j;
        float wv  = lg[j] * inv;
        float cv  = (gc[(size_t)co * HW] - s_mu[co]) * s_rs[co];
        float att = fmaxf(cv * wv, 0.f);
        op[(size_t)co * HW] = att;
        sq = fmaf(s_w2[co], att, sq);
    }
    sq += __shfl_xor_sync(0xffffffffu, sq, 1);
    sq += __shfl_xor_sync(0xffffffffu, sq, 2);
    if (sub == 0) g_sq[p] = sq + c2b[0];
}

// ---------------------------------------------------------------------------
// Kernel 4: window softmax of shape query (zero-padded) + weighted stats
// ---------------------------------------------------------------------------
__global__ __launch_bounds__(256) void agg_kernel(
    const float* __restrict__ x, float* __restrict__ out)
{
    const int p = blockIdx.x * 256 + threadIdx.x;
    if (p >= NPIX) return;
    const int b  = p >> 12;
    const int hw = p & 4095;
    const int h  = hw >> 6;
    const int w  = hw & 63;

    float qv[9];
    float qmax = -3.4e38f;
    #pragma unroll
    for (int i = 0; i < 3; i++)
        #pragma unroll
        for (int j = 0; j < 3; j++) {
            int yy = h + i - 1, xx = w + j - 1;
            float v = 0.f;
            if (yy >= 0 && yy < Hdim && xx >= 0 && xx < Wdim)
                v = g_sq[(b << 12) + (yy << 6) + xx];
            qv[i * 3 + j] = v;
            qmax = fmaxf(qmax, v);
        }
    float qs = 0.f;
    #pragma unroll
    for (int k = 0; k < 9; k++) { qv[k] = __expf(qv[k] - qmax); qs += qv[k]; }
    float qinv = 1.f / qs;
    #pragma unroll
    for (int k = 0; k < 9; k++) qv[k] *= qinv;

    float win[5][9];
    #pragma unroll
    for (int c = 0; c < 5; c++) {
        #pragma unroll
        for (int i = 0; i < 3; i++)
            #pragma unroll
            for (int j = 0; j < 3; j++) {
                int gy = clampi(h + i - 1, 0, Hdim - 1);
                int gx = clampi(w + j - 1, 0, Wdim - 1);
                win[c][i * 3 + j] = x[((b * CTOT + 64 + c) * Hdim + gy) * Wdim + gx];
            }
    }

    float mean0 = 0.f, mean1 = 0.f, v1_0 = 0.f, v1_1 = 0.f, c1 = 0.f;
    #pragma unroll
    for (int k = 0; k < 9; k++) {
        mean0 = fmaf(win[0][k], qv[k], mean0);
        mean1 = fmaf(win[1][k], qv[k], mean1);
        v1_0  = fmaf(win[2][k], qv[k], v1_0);
        v1_1  = fmaf(win[3][k], qv[k], v1_1);
        c1    = fmaf(win[4][k], qv[k], c1);
    }
    float v2_0 = 0.f, v2_1 = 0.f, c2 = 0.f;
    #pragma unroll
    for (int k = 0; k < 9; k++) {
        float d0 = win[0][k] - mean0;
        float d1 = win[1][k] - mean1;
        v2_0 = fmaf(d0 * d0, qv[k], v2_0);
        v2_1 = fmaf(d1 * d1, qv[k], v2_1);
        c2   = fmaf(d0 * d1, qv[k], c2);
    }

    out[((b * CTOT + 64) * Hdim + h) * Wdim + w] = mean0;
    out[((b * CTOT + 65) * Hdim + h) * Wdim + w] = mean1;
    out[((b * CTOT + 66) * Hdim + h) * Wdim + w] = v1_0 + v2_0;
    out[((b * CTOT + 67) * Hdim + h) * Wdim + w] = v1_1 + v2_1;
    out[((b * CTOT + 68) * Hdim + h) * Wdim + w] = c1 + c2;
}

// ---------------------------------------------------------------------------
extern "C" void kernel_launch(void* const* d_in, const int* in_sizes, int n_in,
                              void* d_out, int out_size)
{
    const float* x   = (const float*)d_in[0];
    const float* cw  = (const float*)d_in[1];
    const float* cb  = (const float*)d_in[2];
    const float* c2w = (const float*)d_in[3];
    const float* c2b = (const float*)d_in[4];
    const float* sk  = (const float*)d_in[5];
    float* out = (float*)d_out;

    static bool attr_set = false;
    if (!attr_set) {
        cudaFuncSetAttribute(conv_mma_kernel,
                             cudaFuncAttributeMaxDynamicSharedMemorySize, DYN_SMEM);
        attr_set = true;
    }

    wt_transform<<<144, 256>>>(cw);
    conv_mma_kernel<<<256, 256, DYN_SMEM>>>(x, cb);
    bn_stats<<<64, 256>>>();
    attend_kernel<<<NPIX * 4 / 256, 256>>>(x, sk, c2w, c2b, out);
    agg_kernel<<<NPIX / 256, 256>>>(x, out);
}

// round 10
// speedup vs baseline: 1.3326x; 1.3326x over previous
#include <cuda_runtime.h>
#include <cstdint>

#define BATCH 8
#define CIN   64
#define COUT  64
#define Hdim  64
#define Wdim  64
#define CTOT  69
#define HW    (Hdim*Wdim)
#define NPIX  (BATCH*HW)

// Scratch (static device globals — no allocation)
__device__ float g_conv[BATCH*COUT*HW];   // raw conv output (pre-BN)
__device__ float g_sq[NPIX];              // 1x1-conv "shape query"
__device__ float g_mu[COUT];
__device__ float g_rs[COUT];
__device__ __align__(16) float g_wt[9*4096];  // weights in B-fragment order

__device__ __forceinline__ int clampi(int v, int lo, int hi) {
    return v < lo ? lo : (v > hi ? hi : v);
}
__device__ __forceinline__ float f2tf32f(float f) {
    uint32_t r; asm("cvt.rna.tf32.f32 %0, %1;" : "=r"(r) : "f"(f));
    return __uint_as_float(r);
}

// m16n8k8 tf32 mma: D += A*B (D==C, fp32 accum). a: 4 regs, b: 2 regs.
__device__ __forceinline__ void mma8(float* d, const uint32_t* a, uint32_t b0, uint32_t b1) {
    asm volatile(
        "mma.sync.aligned.m16n8k8.row.col.f32.tf32.tf32.f32 "
        "{%0,%1,%2,%3}, {%4,%5,%6,%7}, {%8,%9}, {%0,%1,%2,%3};\n"
        : "+f"(d[0]), "+f"(d[1]), "+f"(d[2]), "+f"(d[3])
        : "r"(a[0]), "r"(a[1]), "r"(a[2]), "r"(a[3]), "r"(b0), "r"(b1));
}

// ---------------------------------------------------------------------------
// Kernel 0: transform conv weights into B-fragment order (tf32-rounded).
// ---------------------------------------------------------------------------
__global__ __launch_bounds__(256) void wt_transform(const float* __restrict__ cw)
{
    int idx = blockIdx.x * 256 + threadIdx.x;
    if (idx >= 9 * 4096) return;
    int r    = idx & 1;
    int lane = (idx >> 1) & 31;
    int nt   = (idx >> 6) & 7;
    int kk   = (idx >> 9) & 7;
    int kidx = idx >> 12;
    int gid = lane >> 2, tig = lane & 3;
    int co = nt * 8 + gid;
    int ci = kk * 8 + tig + 4 * r;
    g_wt[idx] = f2tf32f(cw[(co * CIN + ci) * 9 + kidx]);
}

// ---------------------------------------------------------------------------
// Kernel 1: 3x3 conv (replication pad) via mma.sync tf32 implicit GEMM.
// (unchanged from 57.3us best)
// ---------------------------------------------------------------------------
#define SLAB_STRIDE 264
#define SLAB_FLOATS (64*SLAB_STRIDE)          // 16896
#define BBUF_FLOATS 4096
#define DYN_SMEM ((SLAB_FLOATS + BBUF_FLOATS) * 4)   // 83968 B

__global__ __launch_bounds__(256, 2) void conv_mma_kernel(
    const float* __restrict__ x, const float* __restrict__ cb)
{
    extern __shared__ float smem[];
    float* slab = smem;
    float* bbuf = smem + SLAB_FLOATS;

    const int tid  = threadIdx.x;
    const int lane = tid & 31;
    const int w    = tid >> 5;
    const int gid  = lane >> 2;
    const int tig  = lane & 3;
    const int wm   = (w & 3) * 32;
    const int wn   = (w >> 2) * 32;
    const int blk  = blockIdx.x;
    const int b    = blk >> 5;
    const int h0   = (blk & 31) * 2;

    const float* xb = x + (size_t)b * CTOT * HW;
    #pragma unroll
    for (int i = 0; i < 64; i++) {
        int idx = i * 256 + tid;
        int ci  = idx >> 8;
        int rc  = idx & 255;
        int rr  = rc >> 6;
        int col = rc & 63;
        int row = clampi(h0 - 1 + rr, 0, Hdim - 1);
        slab[ci * SLAB_STRIDE + rc] = f2tf32f(__ldg(xb + (ci * Hdim + row) * Wdim + col));
    }

    const float4* wt4 = (const float4*)g_wt;
    float4 pf[4];
    #pragma unroll
    for (int j = 0; j < 4; j++) pf[j] = __ldg(wt4 + j * 256 + tid);

    float acc[2][4][4];
    #pragma unroll
    for (int tm = 0; tm < 2; tm++)
        #pragma unroll
        for (int nt = 0; nt < 4; nt++)
            #pragma unroll
            for (int c = 0; c < 4; c++) acc[tm][nt][c] = 0.f;

    __syncthreads();

    int dy[2], col_lo[2], col_hi[2];
    #pragma unroll
    for (int tm = 0; tm < 2; tm++) {
        int pix = wm + tm * 16 + gid;
        dy[tm] = pix >> 6;
        col_lo[tm] = pix & 63;
        col_hi[tm] = col_lo[tm] + 8;
    }

    float4* bb4 = (float4*)bbuf;

    for (int kidx = 0; kidx < 9; kidx++) {
        const int ky = kidx / 3, kx = kidx % 3;
        if (kidx > 0) __syncthreads();
        #pragma unroll
        for (int j = 0; j < 4; j++) bb4[j * 256 + tid] = pf[j];
        __syncthreads();
        if (kidx < 8) {
            #pragma unroll
            for (int j = 0; j < 4; j++)
                pf[j] = __ldg(wt4 + (kidx + 1) * 1024 + j * 256 + tid);
        }

        int off_lo[2], off_hi[2];
        #pragma unroll
        for (int tm = 0; tm < 2; tm++) {
            int rowoff = (dy[tm] + ky) * 64;
            off_lo[tm] = rowoff + clampi(col_lo[tm] + kx - 1, 0, 63);
            off_hi[tm] = rowoff + clampi(col_hi[tm] + kx - 1, 0, 63);
        }

        #pragma unroll
        for (int kk = 0; kk < 8; kk++) {
            const int cib  = (kk * 8 + tig) * SLAB_STRIDE;
            const int cib4 = cib + 4 * SLAB_STRIDE;
            uint32_t a[2][4];
            #pragma unroll
            for (int tm = 0; tm < 2; tm++) {
                a[tm][0] = __float_as_uint(slab[cib  + off_lo[tm]]);
                a[tm][1] = __float_as_uint(slab[cib  + off_hi[tm]]);
                a[tm][2] = __float_as_uint(slab[cib4 + off_lo[tm]]);
                a[tm][3] = __float_as_uint(slab[cib4 + off_hi[tm]]);
            }
            #pragma unroll
            for (int nt = 0; nt < 4; nt++) {
                int ntg = (wn >> 3) + nt;
                float2 bf = *(const float2*)&bbuf[((kk * 8 + ntg) * 32 + lane) * 2];
                uint32_t b0 = __float_as_uint(bf.x);
                uint32_t b1 = __float_as_uint(bf.y);
                mma8(acc[0][nt], a[0], b0, b1);
                mma8(acc[1][nt], a[1], b0, b1);
            }
        }
    }

    #pragma unroll
    for (int tm = 0; tm < 2; tm++) {
        float* grow = g_conv + ((size_t)b * COUT * Hdim + (h0 + dy[tm])) * Wdim;
        #pragma unroll
        for (int nt = 0; nt < 4; nt++) {
            int co0 = wn + nt * 8 + 2 * tig;
            float b0 = __ldg(cb + co0), b1 = __ldg(cb + co0 + 1);
            grow[(size_t)co0       * HW + col_lo[tm]] = acc[tm][nt][0] + b0;
            grow[(size_t)(co0 + 1) * HW + col_lo[tm]] = acc[tm][nt][1] + b1;
            grow[(size_t)co0       * HW + col_hi[tm]] = acc[tm][nt][2] + b0;
            grow[(size_t)(co0 + 1) * HW + col_hi[tm]] = acc[tm][nt][3] + b1;
        }
    }
}

// ---------------------------------------------------------------------------
// Kernel 2: BN stats, one block per channel, deterministic fixed-order tree
// ---------------------------------------------------------------------------
__global__ __launch_bounds__(256) void bn_stats()
{
    __shared__ float ss[256], ss2[256];
    const int co = blockIdx.x;
    const int t  = threadIdx.x;
    float s = 0.f, s2 = 0.f;
    #pragma unroll
    for (int b = 0; b < BATCH; b++) {
        const float4* p = (const float4*)(g_conv + ((size_t)(b * COUT + co)) * HW);
        #pragma unroll
        for (int j = 0; j < 4; j++) {
            float4 v = __ldg(p + t + j * 256);
            s  += v.x + v.y + v.z + v.w;
            s2 += v.x * v.x + v.y * v.y + v.z * v.z + v.w * v.w;
        }
    }
    ss[t] = s; ss2[t] = s2;
    __syncthreads();
    for (int o = 128; o > 0; o >>= 1) {
        if (t < o) { ss[t] += ss[t + o]; ss2[t] += ss2[t + o]; }
        __syncthreads();
    }
    if (t == 0) {
        float n   = (float)(BATCH * HW);
        float mu  = ss[0] / n;
        float var = ss2[0] / n - mu * mu;
        g_mu[co] = mu;
        g_rs[co] = rsqrtf(var + 1e-5f);
    }
}

// ---------------------------------------------------------------------------
// Kernel 3: attend via tensor-core GEMM (3xTF32 for ~fp32 precision).
// Block = 128 threads = 128 pixels, 4 warps (warp strip = 32 pixels).
// logits[128,64] = W[128,45] @ (2*K)[45,64] - |k|^2  via mma.sync m16n8k8:
//   acc = Ahi*Bhi + Alo*Bhi + Ahi*Blo   (lo = residual after tf32 rounding)
// Softmax over codes in C-fragment space (quad shfl over tig lanes).
// Weights transposed through smem (overlaid on dead A buffer); final pass is
// a fully-coalesced per-pixel loop (BN-normalize, relu-attend, 1x1 conv).
// ---------------------------------------------------------------------------
#define AT_AHI   0                       // [128][49]
#define AT_ALO   (128*49)                // [128][49]
#define AT_BHI   (2*128*49)              // [48][65]
#define AT_BLO   (2*128*49 + 48*65)      // [48][65]
#define AT_K2    (2*128*49 + 2*48*65)    // [64]
#define AT_MU    (AT_K2 + 64)
#define AT_RS    (AT_MU + 64)
#define AT_W2    (AT_RS + 64)
#define AT_SMEM_FLOATS (AT_W2 + 64)
#define AT_DYN_SMEM (AT_SMEM_FLOATS * 4)   // ~77.5 KB
#define SW_STRIDE 129                    // sW overlay: [64][129] on A region

__global__ __launch_bounds__(128) void attend_mma_kernel(
    const float* __restrict__ x, const float* __restrict__ sk,
    const float* __restrict__ c2w, const float* __restrict__ c2b,
    float* __restrict__ out)
{
    extern __shared__ float sm[];
    float* sAhi = sm + AT_AHI;
    float* sAlo = sm + AT_ALO;
    float* sBhi = sm + AT_BHI;
    float* sBlo = sm + AT_BLO;
    float* sK2  = sm + AT_K2;
    float* sMu  = sm + AT_MU;
    float* sRs  = sm + AT_RS;
    float* sW2  = sm + AT_W2;
    float* sW   = sm;                    // overlay (after MMA) [64][SW_STRIDE]

    const int tid  = threadIdx.x;
    const int lane = tid & 31;
    const int warp = tid >> 5;
    const int gid  = lane >> 2;
    const int tig  = lane & 3;

    // ---- codebook -> B hi/lo (2*k folded), transposed [k][co]; zero pad ----
    for (int i = tid; i < 64 * 45; i += 128) {
        int co = i / 45, t = i - co * 45;
        float two = 2.f * sk[i];
        float hi  = f2tf32f(two);
        sBhi[t * 65 + co] = hi;
        sBlo[t * 65 + co] = f2tf32f(two - hi);
    }
    for (int i = tid; i < 3 * 65; i += 128) {
        sBhi[45 * 65 + i] = 0.f;
        sBlo[45 * 65 + i] = 0.f;
    }
    if (tid < 64) {
        float a = 0.f;
        #pragma unroll
        for (int t = 0; t < 45; t++) {
            float kv = sk[tid * 45 + t];
            a = fmaf(kv, kv, a);
        }
        sK2[tid] = a;
        sMu[tid] = g_mu[tid];
        sRs[tid] = g_rs[tid];
        sW2[tid] = c2w[tid];
    }

    // ---- per-pixel window build (coalesced LDG), center-subtract ----
    const int p  = blockIdx.x * 128 + tid;
    const int b  = p >> 12;
    const int hw = p & 4095;
    const int h  = hw >> 6;
    const int w  = hw & 63;

    float swv[45];
    #pragma unroll
    for (int c = 0; c < 5; c++) {
        #pragma unroll
        for (int i = 0; i < 3; i++)
            #pragma unroll
            for (int j = 0; j < 3; j++) {
                int gy = clampi(h + i - 1, 0, Hdim - 1);
                int gx = clampi(w + j - 1, 0, Wdim - 1);
                swv[c * 9 + i * 3 + j] = x[((b * CTOT + 64 + c) * Hdim + gy) * Wdim + gx];
            }
    }
    #pragma unroll
    for (int c = 0; c < 2; c++) {
        float ctr = swv[c * 9 + 4];
        #pragma unroll
        for (int k = 0; k < 9; k++) swv[c * 9 + k] -= ctr;
    }
    #pragma unroll
    for (int t = 0; t < 45; t++) {
        float hi = f2tf32f(swv[t]);
        sAhi[tid * 49 + t] = hi;
        sAlo[tid * 49 + t] = f2tf32f(swv[t] - hi);
    }
    #pragma unroll
    for (int t = 45; t < 48; t++) { sAhi[tid * 49 + t] = 0.f; sAlo[tid * 49 + t] = 0.f; }
    __syncthreads();

    // ---- GEMM: warp strip = rows [warp*32, warp*32+32), all 64 cols ----
    float acc[2][8][4];
    #pragma unroll
    for (int mt = 0; mt < 2; mt++)
        #pragma unroll
        for (int nt = 0; nt < 8; nt++)
            #pragma unroll
            for (int c = 0; c < 4; c++) acc[mt][nt][c] = 0.f;

    const int rbase = warp * 32;
    #pragma unroll
    for (int pass = 0; pass < 3; pass++) {
        const float* Ap = (pass == 1) ? sAlo : sAhi;
        const float* Bp = (pass == 2) ? sBlo : sBhi;
        #pragma unroll
        for (int ks = 0; ks < 6; ks++) {
            uint32_t afr[2][4];
            #pragma unroll
            for (int mt = 0; mt < 2; mt++) {
                int r0 = rbase + mt * 16 + gid;
                afr[mt][0] = __float_as_uint(Ap[r0 * 49 + ks * 8 + tig]);
                afr[mt][1] = __float_as_uint(Ap[(r0 + 8) * 49 + ks * 8 + tig]);
                afr[mt][2] = __float_as_uint(Ap[r0 * 49 + ks * 8 + tig + 4]);
                afr[mt][3] = __float_as_uint(Ap[(r0 + 8) * 49 + ks * 8 + tig + 4]);
            }
            #pragma unroll
            for (int nt = 0; nt < 8; nt++) {
                uint32_t b0 = __float_as_uint(Bp[(ks * 8 + tig) * 65 + nt * 8 + gid]);
                uint32_t b1 = __float_as_uint(Bp[(ks * 8 + tig + 4) * 65 + nt * 8 + gid]);
                mma8(acc[0][nt], afr[0], b0, b1);
                mma8(acc[1][nt], afr[1], b0, b1);
            }
        }
    }

    // ---- logits = acc - k2; softmax per row in fragment space ----
    // C frag: c(2*half+cc) = (row gid+8*half, col 2*tig+cc) within (mt,nt) tile
    float wv[2][8][4];   // softmax weights, same layout
    #pragma unroll
    for (int mt = 0; mt < 2; mt++) {
        #pragma unroll
        for (int half = 0; half < 2; half++) {
            float m = -3.4e38f;
            #pragma unroll
            for (int nt = 0; nt < 8; nt++) {
                #pragma unroll
                for (int cc = 0; cc < 2; cc++) {
                    int co = nt * 8 + 2 * tig + cc;
                    float l = acc[mt][nt][2 * half + cc] - sK2[co];
                    acc[mt][nt][2 * half + cc] = l;
                    m = fmaxf(m, l);
                }
            }
            m = fmaxf(m, __shfl_xor_sync(0xffffffffu, m, 1));
            m = fmaxf(m, __shfl_xor_sync(0xffffffffu, m, 2));
            float s = 0.f;
            #pragma unroll
            for (int nt = 0; nt < 8; nt++) {
                #pragma unroll
                for (int cc = 0; cc < 2; cc++) {
                    float e = __expf(acc[mt][nt][2 * half + cc] - m);
                    wv[mt][nt][2 * half + cc] = e;
                    s += e;
                }
            }
            s += __shfl_xor_sync(0xffffffffu, s, 1);
            s += __shfl_xor_sync(0xffffffffu, s, 2);
            float inv = 1.f / s;
            #pragma unroll
            for (int nt = 0; nt < 8; nt++) {
                #pragma unroll
                for (int cc = 0; cc < 2; cc++)
                    wv[mt][nt][2 * half + cc] *= inv;
            }
        }
    }

    __syncthreads();   // all MMA/softmax reads of A/B done -> safe to overlay

    // ---- transpose weights to sW[co][pix] ----
    #pragma unroll
    for (int mt = 0; mt < 2; mt++) {
        #pragma unroll
        for (int half = 0; half < 2; half++) {
            int pix = rbase + mt * 16 + gid + 8 * half;
            #pragma unroll
            for (int nt = 0; nt < 8; nt++) {
                #pragma unroll
                for (int cc = 0; cc < 2; cc++) {
                    int co = nt * 8 + 2 * tig + cc;
                    sW[co * SW_STRIDE + pix] = wv[mt][nt][2 * half + cc];
                }
            }
        }
    }
    __syncthreads();

    // ---- final coalesced pass: BN-normalize, relu-attend, 1x1 conv ----
    const float* gc = g_conv + (size_t)b * COUT * HW + hw;
    float* op = out + (size_t)b * CTOT * HW + hw;
    float sq = __ldg(c2b);
    #pragma unroll 4
    for (int co = 0; co < 64; co++) {
        float ww  = sW[co * SW_STRIDE + tid];
        float cv  = (gc[(size_t)co * HW] - sMu[co]) * sRs[co];
        float att = fmaxf(cv * ww, 0.f);
        op[(size_t)co * HW] = att;
        sq = fmaf(sW2[co], att, sq);
    }
    g_sq[p] = sq;
}

// ---------------------------------------------------------------------------
// Kernel 4: window softmax of shape query (zero-padded) + weighted stats
// ---------------------------------------------------------------------------
__global__ __launch_bounds__(256) void agg_kernel(
    const float* __restrict__ x, float* __restrict__ out)
{
    const int p = blockIdx.x * 256 + threadIdx.x;
    if (p >= NPIX) return;
    const int b  = p >> 12;
    const int hw = p & 4095;
    const int h  = hw >> 6;
    const int w  = hw & 63;

    float qv[9];
    float qmax = -3.4e38f;
    #pragma unroll
    for (int i = 0; i < 3; i++)
        #pragma unroll
        for (int j = 0; j < 3; j++) {
            int yy = h + i - 1, xx = w + j - 1;
            float v = 0.f;
            if (yy >= 0 && yy < Hdim && xx >= 0 && xx < Wdim)
                v = g_sq[(b << 12) + (yy << 6) + xx];
            qv[i * 3 + j] = v;
            qmax = fmaxf(qmax, v);
        }
    float qs = 0.f;
    #pragma unroll
    for (int k = 0; k < 9; k++) { qv[k] = __expf(qv[k] - qmax); qs += qv[k]; }
    float qinv = 1.f / qs;
    #pragma unroll
    for (int k = 0; k < 9; k++) qv[k] *= qinv;

    float win[5][9];
    #pragma unroll
    for (int c = 0; c < 5; c++) {
        #pragma unroll
        for (int i = 0; i < 3; i++)
            #pragma unroll
            for (int j = 0; j < 3; j++) {
                int gy = clampi(h + i - 1, 0, Hdim - 1);
                int gx = clampi(w + j - 1, 0, Wdim - 1);
                win[c][i * 3 + j] = x[((b * CTOT + 64 + c) * Hdim + gy) * Wdim + gx];
            }
    }

    float mean0 = 0.f, mean1 = 0.f, v1_0 = 0.f, v1_1 = 0.f, c1 = 0.f;
    #pragma unroll
    for (int k = 0; k < 9; k++) {
        mean0 = fmaf(win[0][k], qv[k], mean0);
        mean1 = fmaf(win[1][k], qv[k], mean1);
        v1_0  = fmaf(win[2][k], qv[k], v1_0);
        v1_1  = fmaf(win[3][k], qv[k], v1_1);
        c1    = fmaf(win[4][k], qv[k], c1);
    }
    float v2_0 = 0.f, v2_1 = 0.f, c2 = 0.f;
    #pragma unroll
    for (int k = 0; k < 9; k++) {
        float d0 = win[0][k] - mean0;
        float d1 = win[1][k] - mean1;
        v2_0 = fmaf(d0 * d0, qv[k], v2_0);
        v2_1 = fmaf(d1 * d1, qv[k], v2_1);
        c2   = fmaf(d0 * d1, qv[k], c2);
    }

    out[((b * CTOT + 64) * Hdim + h) * Wdim + w] = mean0;
    out[((b * CTOT + 65) * Hdim + h) * Wdim + w] = mean1;
    out[((b * CTOT + 66) * Hdim + h) * Wdim + w] = v1_0 + v2_0;
    out[((b * CTOT + 67) * Hdim + h) * Wdim + w] = v1_1 + v2_1;
    out[((b * CTOT + 68) * Hdim + h) * Wdim + w] = c1 + c2;
}

// ---------------------------------------------------------------------------
extern "C" void kernel_launch(void* const* d_in, const int* in_sizes, int n_in,
                              void* d_out, int out_size)
{
    const float* x   = (const float*)d_in[0];
    const float* cw  = (const float*)d_in[1];
    const float* cb  = (const float*)d_in[2];
    const float* c2w = (const float*)d_in[3];
    const float* c2b = (const float*)d_in[4];
    const float* sk  = (const float*)d_in[5];
    float* out = (float*)d_out;

    static bool attr_set = false;
    if (!attr_set) {
        cudaFuncSetAttribute(conv_mma_kernel,
                             cudaFuncAttributeMaxDynamicSharedMemorySize, DYN_SMEM);
        cudaFuncSetAttribute(attend_mma_kernel,
                             cudaFuncAttributeMaxDynamicSharedMemorySize, AT_DYN_SMEM);
        attr_set = true;
    }

    wt_transform<<<144, 256>>>(cw);
    conv_mma_kernel<<<256, 256, DYN_SMEM>>>(x, cb);
    bn_stats<<<64, 256>>>();
    attend_mma_kernel<<<NPIX / 128, 128, AT_DYN_SMEM>>>(x, sk, c2w, c2b, out);
    agg_kernel<<<NPIX / 256, 256>>>(x, out);
}

// round 11
// speedup vs baseline: 1.4990x; 1.1249x over previous
#include <cuda_runtime.h>
#include <cstdint>

#define BATCH 8
#define CIN   64
#define COUT  64
#define Hdim  64
#define Wdim  64
#define CTOT  69
#define HW    (Hdim*Wdim)
#define NPIX  (BATCH*HW)

// Scratch (static device globals — no allocation)
__device__ float g_conv[BATCH*COUT*HW];   // raw conv output (pre-BN)
__device__ float g_sq[NPIX];              // 1x1-conv "shape query"
__device__ float g_mu[COUT];
__device__ float g_rs[COUT];
__device__ __align__(16) float g_wt[9*4096];  // weights in B-fragment order

__device__ __forceinline__ int clampi(int v, int lo, int hi) {
    return v < lo ? lo : (v > hi ? hi : v);
}
__device__ __forceinline__ float f2tf32f(float f) {
    uint32_t r; asm("cvt.rna.tf32.f32 %0, %1;" : "=r"(r) : "f"(f));
    return __uint_as_float(r);
}

// m16n8k8 tf32 mma: D += A*B (D==C, fp32 accum). a: 4 regs, b: 2 regs.
__device__ __forceinline__ void mma8(float* d, const uint32_t* a, uint32_t b0, uint32_t b1) {
    asm volatile(
        "mma.sync.aligned.m16n8k8.row.col.f32.tf32.tf32.f32 "
        "{%0,%1,%2,%3}, {%4,%5,%6,%7}, {%8,%9}, {%0,%1,%2,%3};\n"
        : "+f"(d[0]), "+f"(d[1]), "+f"(d[2]), "+f"(d[3])
        : "r"(a[0]), "r"(a[1]), "r"(a[2]), "r"(a[3]), "r"(b0), "r"(b1));
}

// ---------------------------------------------------------------------------
// Kernel 0: transform conv weights into B-fragment order (tf32-rounded).
// ---------------------------------------------------------------------------
__global__ __launch_bounds__(256) void wt_transform(const float* __restrict__ cw)
{
    int idx = blockIdx.x * 256 + threadIdx.x;
    if (idx >= 9 * 4096) return;
    int r    = idx & 1;
    int lane = (idx >> 1) & 31;
    int nt   = (idx >> 6) & 7;
    int kk   = (idx >> 9) & 7;
    int kidx = idx >> 12;
    int gid = lane >> 2, tig = lane & 3;
    int co = nt * 8 + gid;
    int ci = kk * 8 + tig + 4 * r;
    g_wt[idx] = f2tf32f(cw[(co * CIN + ci) * 9 + kidx]);
}

// ---------------------------------------------------------------------------
// Kernel 1: 3x3 conv (replication pad) via mma.sync tf32 implicit GEMM.
// (unchanged from 55.3us best)
// ---------------------------------------------------------------------------
#define SLAB_STRIDE 264
#define SLAB_FLOATS (64*SLAB_STRIDE)
#define BBUF_FLOATS 4096
#define DYN_SMEM ((SLAB_FLOATS + BBUF_FLOATS) * 4)

__global__ __launch_bounds__(256, 2) void conv_mma_kernel(
    const float* __restrict__ x, const float* __restrict__ cb)
{
    extern __shared__ float smem[];
    float* slab = smem;
    float* bbuf = smem + SLAB_FLOATS;

    const int tid  = threadIdx.x;
    const int lane = tid & 31;
    const int w    = tid >> 5;
    const int gid  = lane >> 2;
    const int tig  = lane & 3;
    const int wm   = (w & 3) * 32;
    const int wn   = (w >> 2) * 32;
    const int blk  = blockIdx.x;
    const int b    = blk >> 5;
    const int h0   = (blk & 31) * 2;

    const float* xb = x + (size_t)b * CTOT * HW;
    #pragma unroll
    for (int i = 0; i < 64; i++) {
        int idx = i * 256 + tid;
        int ci  = idx >> 8;
        int rc  = idx & 255;
        int rr  = rc >> 6;
        int col = rc & 63;
        int row = clampi(h0 - 1 + rr, 0, Hdim - 1);
        slab[ci * SLAB_STRIDE + rc] = f2tf32f(__ldg(xb + (ci * Hdim + row) * Wdim + col));
    }

    const float4* wt4 = (const float4*)g_wt;
    float4 pf[4];
    #pragma unroll
    for (int j = 0; j < 4; j++) pf[j] = __ldg(wt4 + j * 256 + tid);

    float acc[2][4][4];
    #pragma unroll
    for (int tm = 0; tm < 2; tm++)
        #pragma unroll
        for (int nt = 0; nt < 4; nt++)
            #pragma unroll
            for (int c = 0; c < 4; c++) acc[tm][nt][c] = 0.f;

    __syncthreads();

    int dy[2], col_lo[2], col_hi[2];
    #pragma unroll
    for (int tm = 0; tm < 2; tm++) {
        int pix = wm + tm * 16 + gid;
        dy[tm] = pix >> 6;
        col_lo[tm] = pix & 63;
        col_hi[tm] = col_lo[tm] + 8;
    }

    float4* bb4 = (float4*)bbuf;

    for (int kidx = 0; kidx < 9; kidx++) {
        const int ky = kidx / 3, kx = kidx % 3;
        if (kidx > 0) __syncthreads();
        #pragma unroll
        for (int j = 0; j < 4; j++) bb4[j * 256 + tid] = pf[j];
        __syncthreads();
        if (kidx < 8) {
            #pragma unroll
            for (int j = 0; j < 4; j++)
                pf[j] = __ldg(wt4 + (kidx + 1) * 1024 + j * 256 + tid);
        }

        int off_lo[2], off_hi[2];
        #pragma unroll
        for (int tm = 0; tm < 2; tm++) {
            int rowoff = (dy[tm] + ky) * 64;
            off_lo[tm] = rowoff + clampi(col_lo[tm] + kx - 1, 0, 63);
            off_hi[tm] = rowoff + clampi(col_hi[tm] + kx - 1, 0, 63);
        }

        #pragma unroll
        for (int kk = 0; kk < 8; kk++) {
            const int cib  = (kk * 8 + tig) * SLAB_STRIDE;
            const int cib4 = cib + 4 * SLAB_STRIDE;
            uint32_t a[2][4];
            #pragma unroll
            for (int tm = 0; tm < 2; tm++) {
                a[tm][0] = __float_as_uint(slab[cib  + off_lo[tm]]);
                a[tm][1] = __float_as_uint(slab[cib  + off_hi[tm]]);
                a[tm][2] = __float_as_uint(slab[cib4 + off_lo[tm]]);
                a[tm][3] = __float_as_uint(slab[cib4 + off_hi[tm]]);
            }
            #pragma unroll
            for (int nt = 0; nt < 4; nt++) {
                int ntg = (wn >> 3) + nt;
                float2 bf = *(const float2*)&bbuf[((kk * 8 + ntg) * 32 + lane) * 2];
                uint32_t b0 = __float_as_uint(bf.x);
                uint32_t b1 = __float_as_uint(bf.y);
                mma8(acc[0][nt], a[0], b0, b1);
                mma8(acc[1][nt], a[1], b0, b1);
            }
        }
    }

    #pragma unroll
    for (int tm = 0; tm < 2; tm++) {
        float* grow = g_conv + ((size_t)b * COUT * Hdim + (h0 + dy[tm])) * Wdim;
        #pragma unroll
        for (int nt = 0; nt < 4; nt++) {
            int co0 = wn + nt * 8 + 2 * tig;
            float b0 = __ldg(cb + co0), b1 = __ldg(cb + co0 + 1);
            grow[(size_t)co0       * HW + col_lo[tm]] = acc[tm][nt][0] + b0;
            grow[(size_t)(co0 + 1) * HW + col_lo[tm]] = acc[tm][nt][1] + b1;
            grow[(size_t)co0       * HW + col_hi[tm]] = acc[tm][nt][2] + b0;
            grow[(size_t)(co0 + 1) * HW + col_hi[tm]] = acc[tm][nt][3] + b1;
        }
    }
}

// ---------------------------------------------------------------------------
// Kernel 2: BN stats (unchanged)
// ---------------------------------------------------------------------------
__global__ __launch_bounds__(256) void bn_stats()
{
    __shared__ float ss[256], ss2[256];
    const int co = blockIdx.x;
    const int t  = threadIdx.x;
    float s = 0.f, s2 = 0.f;
    #pragma unroll
    for (int b = 0; b < BATCH; b++) {
        const float4* p = (const float4*)(g_conv + ((size_t)(b * COUT + co)) * HW);
        #pragma unroll
        for (int j = 0; j < 4; j++) {
            float4 v = __ldg(p + t + j * 256);
            s  += v.x + v.y + v.z + v.w;
            s2 += v.x * v.x + v.y * v.y + v.z * v.z + v.w * v.w;
        }
    }
    ss[t] = s; ss2[t] = s2;
    __syncthreads();
    for (int o = 128; o > 0; o >>= 1) {
        if (t < o) { ss[t] += ss[t + o]; ss2[t] += ss2[t + o]; }
        __syncthreads();
    }
    if (t == 0) {
        float n   = (float)(BATCH * HW);
        float mu  = ss[0] / n;
        float var = ss2[0] / n - mu * mu;
        g_mu[co] = mu;
        g_rs[co] = rsqrtf(var + 1e-5f);
    }
}

// ---------------------------------------------------------------------------
// Kernel 3: attend via 3xTF32 mma.sync, code-split warp pairs.
// Block = 256 threads / 128 pixels. Warp pair (w, w^1) shares a 32-pixel
// strip; each warp owns 32 of the 64 codes (4 n8 tiles). A and B are stored
// in smem as FP32 originals; hi/lo tf32 parts derived in registers.
// Softmax combined across the pair via smem partials. Weights transposed
// into an sW overlay; final pass fully coalesced with co-split halves.
// ---------------------------------------------------------------------------
#define A2_STRIDE 52
#define B2_STRIDE 72
#define SW2_STRIDE 130
#define AT2_A    0                         // [128][52]
#define AT2_B    (128*A2_STRIDE)           // 6656 ; [48][72]
#define AT2_REGION (6656 + 48*B2_STRIDE)   // 10112 (overlay sW = 64*130 = 8320 fits)
#define AT2_REDM AT2_REGION                // [256]
#define AT2_REDS (AT2_REDM + 256)          // [256]
#define AT2_SQP  (AT2_REDS + 256)          // [128]
#define AT2_K2   (AT2_SQP + 128)           // [64]
#define AT2_MU   (AT2_K2 + 64)
#define AT2_RS   (AT2_MU + 64)
#define AT2_W2   (AT2_RS + 64)
#define AT2_FLOATS (AT2_W2 + 64)
#define AT2_DYN_SMEM (AT2_FLOATS * 4)      // ~44 KB

__global__ __launch_bounds__(256, 2) void attend_mma_kernel(
    const float* __restrict__ x, const float* __restrict__ sk,
    const float* __restrict__ c2w, const float* __restrict__ c2b,
    float* __restrict__ out)
{
    extern __shared__ float sm[];
    float* sA   = sm + AT2_A;
    float* sB   = sm + AT2_B;
    float* sW   = sm;                      // overlay after MMA
    float* sRm  = sm + AT2_REDM;
    float* sRs_ = sm + AT2_REDS;
    float* sSQP = sm + AT2_SQP;
    float* sK2  = sm + AT2_K2;
    float* sMu  = sm + AT2_MU;
    float* sRs  = sm + AT2_RS;
    float* sW2  = sm + AT2_W2;

    const int tid  = threadIdx.x;
    const int lane = tid & 31;
    const int warp = tid >> 5;
    const int gid  = lane >> 2;
    const int tig  = lane & 3;

    // ---- B setup: 2*codebook transposed [k][co], fp32; pad rows zero ----
    for (int i = tid; i < 64 * 45; i += 256) {
        int co = i / 45, t = i - co * 45;
        sB[t * B2_STRIDE + co] = 2.f * sk[i];
    }
    for (int i = tid; i < 3 * B2_STRIDE; i += 256) sB[45 * B2_STRIDE + i] = 0.f;
    if (tid < 64) {
        float a = 0.f;
        #pragma unroll
        for (int t = 0; t < 45; t++) {
            float kv = sk[tid * 45 + t];
            a = fmaf(kv, kv, a);
        }
        sK2[tid] = a;
        sMu[tid] = g_mu[tid];
        sRs[tid] = g_rs[tid];
        sW2[tid] = c2w[tid];
    }

    // ---- window build: half 0 -> c=0,1 (center-subtract) + pad; half 1 -> c=2..4
    const int pix  = tid & 127;
    const int half = tid >> 7;
    const int p    = blockIdx.x * 128 + pix;
    const int b    = p >> 12;
    const int hw   = p & 4095;
    const int h    = hw >> 6;
    const int w    = hw & 63;

    if (half == 0) {
        #pragma unroll
        for (int c = 0; c < 2; c++) {
            float v[9];
            #pragma unroll
            for (int i = 0; i < 3; i++)
                #pragma unroll
                for (int j = 0; j < 3; j++) {
                    int gy = clampi(h + i - 1, 0, Hdim - 1);
                    int gx = clampi(w + j - 1, 0, Wdim - 1);
                    v[i * 3 + j] = x[((b * CTOT + 64 + c) * Hdim + gy) * Wdim + gx];
                }
            float ctr = v[4];
            #pragma unroll
            for (int k = 0; k < 9; k++) sA[pix * A2_STRIDE + c * 9 + k] = v[k] - ctr;
        }
        #pragma unroll
        for (int t = 45; t < 48; t++) sA[pix * A2_STRIDE + t] = 0.f;
    } else {
        #pragma unroll
        for (int c = 2; c < 5; c++) {
            #pragma unroll
            for (int i = 0; i < 3; i++)
                #pragma unroll
                for (int j = 0; j < 3; j++) {
                    int gy = clampi(h + i - 1, 0, Hdim - 1);
                    int gx = clampi(w + j - 1, 0, Wdim - 1);
                    sA[pix * A2_STRIDE + c * 9 + i * 3 + j] =
                        x[((b * CTOT + 64 + c) * Hdim + gy) * Wdim + gx];
                }
        }
    }
    __syncthreads();

    // ---- MMA: warp pair (warp>>1) strip of 32 rows; coHalf = warp&1 ----
    const int rstrip = (warp >> 1) * 32;
    const int coHalf = warp & 1;
    const int nt0    = coHalf * 4;

    float acc[2][4][4];
    #pragma unroll
    for (int mt = 0; mt < 2; mt++)
        #pragma unroll
        for (int nt = 0; nt < 4; nt++)
            #pragma unroll
            for (int c = 0; c < 4; c++) acc[mt][nt][c] = 0.f;

    #pragma unroll
    for (int ks = 0; ks < 6; ks++) {
        uint32_t ah[2][4], al[2][4];
        #pragma unroll
        for (int mt = 0; mt < 2; mt++) {
            int r0 = rstrip + mt * 16 + gid;
            float o0 = sA[r0 * A2_STRIDE + ks * 8 + tig];
            float o1 = sA[(r0 + 8) * A2_STRIDE + ks * 8 + tig];
            float o2 = sA[r0 * A2_STRIDE + ks * 8 + tig + 4];
            float o3 = sA[(r0 + 8) * A2_STRIDE + ks * 8 + tig + 4];
            float h0 = f2tf32f(o0), h1 = f2tf32f(o1), h2 = f2tf32f(o2), h3 = f2tf32f(o3);
            ah[mt][0] = __float_as_uint(h0); al[mt][0] = __float_as_uint(f2tf32f(o0 - h0));
            ah[mt][1] = __float_as_uint(h1); al[mt][1] = __float_as_uint(f2tf32f(o1 - h1));
            ah[mt][2] = __float_as_uint(h2); al[mt][2] = __float_as_uint(f2tf32f(o2 - h2));
            ah[mt][3] = __float_as_uint(h3); al[mt][3] = __float_as_uint(f2tf32f(o3 - h3));
        }
        #pragma unroll
        for (int ntl = 0; ntl < 4; ntl++) {
            int nt = nt0 + ntl;
            float bo0 = sB[(ks * 8 + tig) * B2_STRIDE + nt * 8 + gid];
            float bo1 = sB[(ks * 8 + tig + 4) * B2_STRIDE + nt * 8 + gid];
            float bh0 = f2tf32f(bo0), bh1 = f2tf32f(bo1);
            uint32_t uh0 = __float_as_uint(bh0), uh1 = __float_as_uint(bh1);
            uint32_t ul0 = __float_as_uint(f2tf32f(bo0 - bh0));
            uint32_t ul1 = __float_as_uint(f2tf32f(bo1 - bh1));
            #pragma unroll
            for (int mt = 0; mt < 2; mt++) {
                mma8(acc[mt][ntl], ah[mt], uh0, uh1);
                mma8(acc[mt][ntl], al[mt], uh0, uh1);
                mma8(acc[mt][ntl], ah[mt], ul0, ul1);
            }
        }
    }
    __syncthreads();   // all A/B reads done (before sW overlay writes)

    // ---- softmax phase 1: logits & per-warp partial max ----
    #pragma unroll
    for (int mt = 0; mt < 2; mt++) {
        #pragma unroll
        for (int h8 = 0; h8 < 2; h8++) {
            float m = -3.4e38f;
            #pragma unroll
            for (int ntl = 0; ntl < 4; ntl++) {
                #pragma unroll
                for (int cc = 0; cc < 2; cc++) {
                    int co = coHalf * 32 + ntl * 8 + 2 * tig + cc;
                    float l = acc[mt][ntl][2 * h8 + cc] - sK2[co];
                    acc[mt][ntl][2 * h8 + cc] = l;
                    m = fmaxf(m, l);
                }
            }
            m = fmaxf(m, __shfl_xor_sync(0xffffffffu, m, 1));
            m = fmaxf(m, __shfl_xor_sync(0xffffffffu, m, 2));
            if (tig == 0) {
                int row = rstrip + mt * 16 + gid + 8 * h8;
                sRm[coHalf * 128 + row] = m;
            }
        }
    }
    __syncthreads();

    // ---- phase 2: combined max, exp, partial sums ----
    #pragma unroll
    for (int mt = 0; mt < 2; mt++) {
        #pragma unroll
        for (int h8 = 0; h8 < 2; h8++) {
            int row = rstrip + mt * 16 + gid + 8 * h8;
            float m = fmaxf(sRm[row], sRm[128 + row]);
            float s = 0.f;
            #pragma unroll
            for (int ntl = 0; ntl < 4; ntl++) {
                #pragma unroll
                for (int cc = 0; cc < 2; cc++) {
                    float e = __expf(acc[mt][ntl][2 * h8 + cc] - m);
                    acc[mt][ntl][2 * h8 + cc] = e;
                    s += e;
                }
            }
            s += __shfl_xor_sync(0xffffffffu, s, 1);
            s += __shfl_xor_sync(0xffffffffu, s, 2);
            if (tig == 0) sRs_[coHalf * 128 + row] = s;
        }
    }
    __syncthreads();

    // ---- phase 3: normalize & transpose into sW[co][row] ----
    #pragma unroll
    for (int mt = 0; mt < 2; mt++) {
        #pragma unroll
        for (int h8 = 0; h8 < 2; h8++) {
            int row = rstrip + mt * 16 + gid + 8 * h8;
            float inv = 1.f / (sRs_[row] + sRs_[128 + row]);
            #pragma unroll
            for (int ntl = 0; ntl < 4; ntl++) {
                #pragma unroll
                for (int cc = 0; cc < 2; cc++) {
                    int co = coHalf * 32 + ntl * 8 + 2 * tig + cc;
                    sW[co * SW2_STRIDE + row] = acc[mt][ntl][2 * h8 + cc] * inv;
                }
            }
        }
    }
    __syncthreads();

    // ---- final coalesced pass: co-range split across thread halves ----
    const float* gc = g_conv + (size_t)b * COUT * HW + hw;
    float* op = out + (size_t)b * CTOT * HW + hw;
    float sq = 0.f;
    const int cb0 = half * 32;
    #pragma unroll 4
    for (int j = 0; j < 32; j++) {
        int co = cb0 + j;
        float ww  = sW[co * SW2_STRIDE + pix];
        float cv  = (gc[(size_t)co * HW] - sMu[co]) * sRs[co];
        float att = fmaxf(cv * ww, 0.f);
        op[(size_t)co * HW] = att;
        sq = fmaf(sW2[co], att, sq);
    }
    if (half == 1) sSQP[pix] = sq;
    __syncthreads();
    if (half == 0) g_sq[p] = sq + sSQP[pix] + __ldg(c2b);
}

// ---------------------------------------------------------------------------
// Kernel 4: window softmax of shape query (zero-padded) + weighted stats
// ---------------------------------------------------------------------------
__global__ __launch_bounds__(256) void agg_kernel(
    const float* __restrict__ x, float* __restrict__ out)
{
    const int p = blockIdx.x * 256 + threadIdx.x;
    if (p >= NPIX) return;
    const int b  = p >> 12;
    const int hw = p & 4095;
    const int h  = hw >> 6;
    const int w  = hw & 63;

    float qv[9];
    float qmax = -3.4e38f;
    #pragma unroll
    for (int i = 0; i < 3; i++)
        #pragma unroll
        for (int j = 0; j < 3; j++) {
            int yy = h + i - 1, xx = w + j - 1;
            float v = 0.f;
            if (yy >= 0 && yy < Hdim && xx >= 0 && xx < Wdim)
                v = g_sq[(b << 12) + (yy << 6) + xx];
            qv[i * 3 + j] = v;
            qmax = fmaxf(qmax, v);
        }
    float qs = 0.f;
    #pragma unroll
    for (int k = 0; k < 9; k++) { qv[k] = __expf(qv[k] - qmax); qs += qv[k]; }
    float qinv = 1.f / qs;
    #pragma unroll
    for (int k = 0; k < 9; k++) qv[k] *= qinv;

    float win[5][9];
    #pragma unroll
    for (int c = 0; c < 5; c++) {
        #pragma unroll
        for (int i = 0; i < 3; i++)
            #pragma unroll
            for (int j = 0; j < 3; j++) {
                int gy = clampi(h + i - 1, 0, Hdim - 1);
                int gx = clampi(w + j - 1, 0, Wdim - 1);
                win[c][i * 3 + j] = x[((b * CTOT + 64 + c) * Hdim + gy) * Wdim + gx];
            }
    }

    float mean0 = 0.f, mean1 = 0.f, v1_0 = 0.f, v1_1 = 0.f, c1 = 0.f;
    #pragma unroll
    for (int k = 0; k < 9; k++) {
        mean0 = fmaf(win[0][k], qv[k], mean0);
        mean1 = fmaf(win[1][k], qv[k], mean1);
        v1_0  = fmaf(win[2][k], qv[k], v1_0);
        v1_1  = fmaf(win[3][k], qv[k], v1_1);
        c1    = fmaf(win[4][k], qv[k], c1);
    }
    float v2_0 = 0.f, v2_1 = 0.f, c2 = 0.f;
    #pragma unroll
    for (int k = 0; k < 9; k++) {
        float d0 = win[0][k] - mean0;
        float d1 = win[1][k] - mean1;
        v2_0 = fmaf(d0 * d0, qv[k], v2_0);
        v2_1 = fmaf(d1 * d1, qv[k], v2_1);
        c2   = fmaf(d0 * d1, qv[k], c2);
    }

    out[((b * CTOT + 64) * Hdim + h) * Wdim + w] = mean0;
    out[((b * CTOT + 65) * Hdim + h) * Wdim + w] = mean1;
    out[((b * CTOT + 66) * Hdim + h) * Wdim + w] = v1_0 + v2_0;
    out[((b * CTOT + 67) * Hdim + h) * Wdim + w] = v1_1 + v2_1;
    out[((b * CTOT + 68) * Hdim + h) * Wdim + w] = c1 + c2;
}

// ---------------------------------------------------------------------------
extern "C" void kernel_launch(void* const* d_in, const int* in_sizes, int n_in,
                              void* d_out, int out_size)
{
    const float* x   = (const float*)d_in[0];
    const float* cw  = (const float*)d_in[1];
    const float* cb  = (const float*)d_in[2];
    const float* c2w = (const float*)d_in[3];
    const float* c2b = (const float*)d_in[4];
    const float* sk  = (const float*)d_in[5];
    float* out = (float*)d_out;

    static bool attr_set = false;
    if (!attr_set) {
        cudaFuncSetAttribute(conv_mma_kernel,
                             cudaFuncAttributeMaxDynamicSharedMemorySize, DYN_SMEM);
        cudaFuncSetAttribute(attend_mma_kernel,
                             cudaFuncAttributeMaxDynamicSharedMemorySize, AT2_DYN_SMEM);
        attr_set = true;
    }

    wt_transform<<<144, 256>>>(cw);
    conv_mma_kernel<<<256, 256, DYN_SMEM>>>(x, cb);
    bn_stats<<<64, 256>>>();
    attend_mma_kernel<<<NPIX / 128, 256, AT2_DYN_SMEM>>>(x, sk, c2w, c2b, out);
    agg_kernel<<<NPIX / 256, 256>>>(x, out);
}